// round 17
// baseline (speedup 1.0000x reference)
#include <cuda_runtime.h>

// MultiScaleMovingAvg via per-thread running box sums.  FINAL (= R11/R14/R15/R16).
//
// Design: each warp owns 64 channels; per-thread packed-f32x2 running sums for
// the 4 box windows (k=3,7,15,31; O(1) per output via sliding-window update),
// fed by a warp-autonomous cp.async pipeline into a 32-row smem ring
// (precise wait_group ordering -> real MLP; 2 groups / 16 rows in flight).
// st.global.cs stores (eager writeback keeps graph replays independent),
// L2::evict_first on the single-use read stream, clamp-free producer for
// interior CTAs (replicate-pad handled at fill time).
//
// Measured landscape (R5-R16): kernel pinned at ~5.5TB/s DRAM across 6
// structurally different designs with all SM-side pipes <50% -> mixed-R/W
// HBM bus equilibrium; traffic is mandatory (134MB read + 134MB write,
// 6.25% halo). SEG=512 is the knee: SEG=1024 drops chip-wide in-flight
// bytes to the BW-delay floor (R12); RING=64 bloats I$ (R13); deeper
// pending on RING=32 aliases read slots (unsafe). Floor: ~46us wall.

#define B_DIM 16
#define S_DIM 4096
#define F_DIM 512
#define SEG   512
#define TPB   64
#define RING  32

typedef unsigned long long u64;

#define ADD2(d, a, b)    asm("add.rn.f32x2 %0, %1, %2;" : "=l"(d) : "l"(a), "l"(b))
#define SUB2(d, a, b)    asm("sub.rn.f32x2 %0, %1, %2;" : "=l"(d) : "l"(a), "l"(b))
#define MUL2(d, a, b)    asm("mul.rn.f32x2 %0, %1, %2;" : "=l"(d) : "l"(a), "l"(b))
#define FMA2(d, a, b, c) asm("fma.rn.f32x2 %0, %1, %2, %3;" : "=l"(d) : "l"(a), "l"(b), "l"(c))

__device__ __forceinline__ u64 pack2(float v) {
    u64 r;
    asm("mov.b64 %0, {%1, %1};" : "=l"(r) : "f"(v));
    return r;
}
__device__ __forceinline__ void stg_cs64(u64* p, u64 v) {
    asm volatile("st.global.cs.b64 [%0], %1;" :: "l"(p), "l"(v) : "memory");
}
__device__ __forceinline__ u64 mk_evict_first_policy() {
    u64 pol;
    asm("createpolicy.fractional.L2::evict_first.b64 %0, 1.0;" : "=l"(pol));
    return pol;
}
__device__ __forceinline__ void cp_async16_ef(unsigned saddr, const void* gptr,
                                              u64 pol) {
    asm volatile("cp.async.cg.shared.global.L2::cache_hint [%0], [%1], 16, %2;\n"
                 :: "r"(saddr), "l"(gptr), "l"(pol));
}
__device__ __forceinline__ void cp_commit() {
    asm volatile("cp.async.commit_group;\n");
}
template <int N>
__device__ __forceinline__ void cp_wait() {
    asm volatile("cp.async.wait_group %0;\n" :: "n"(N));
}

struct Prod {
    const float* xb;     // batch base
    u64 pol;             // L2 evict_first policy (reads)
    unsigned rbase;      // smem ring base (this warp)
    unsigned pbyte;      // lane byte offset within row
    int prow, pcolf, f0;

    // clamped issue (prologue / last Y-block): row clamped to [0, S-1]
    __device__ __forceinline__ void issue_clamped(int r) const {
        #pragma unroll
        for (int j = 0; j < 4; ++j) {
            int rr = r + 2 * j + prow;
            int cc = rr < 0 ? 0 : (rr > S_DIM - 1 ? S_DIM - 1 : rr);
            unsigned da = rbase + ((unsigned)(rr & (RING - 1)) << 8) + pbyte;
            cp_async16_ef(da, xb + (size_t)cc * F_DIM + f0 + pcolf, pol);
        }
        cp_commit();
    }
    // fast issue (interior): no clamping needed
    __device__ __forceinline__ void issue_fast(int r) const {
        const float* g = xb + (size_t)(r + prow) * F_DIM + f0 + pcolf;
        #pragma unroll
        for (int j = 0; j < 4; ++j) {
            int rr = r + 2 * j + prow;
            unsigned da = rbase + ((unsigned)(rr & (RING - 1)) << 8) + pbyte;
            cp_async16_ef(da, g + (size_t)(2 * j) * F_DIM, pol);
        }
        cp_commit();
    }
};

template <bool CLAMP>
__device__ __forceinline__ void main_loop(
    const Prod& P, u64 (* __restrict__ rw)[32], int lane, int s0,
    u64* __restrict__ op, u64* Q,
    u64 C3, u64 C7, u64 C15, u64 C31,
    u64& W3, u64& W7, u64& W15, u64& W31)
{
    #pragma unroll 1
    for (int ob = 0; ob < SEG / 32; ++ob) {
        #pragma unroll
        for (int h = 0; h < 2; ++h) {
            const int PAR   = h * 16;                // compile-time
            const int p_rel = ob * 32 + PAR;

            #pragma unroll
            for (int u = 0; u < 16; ++u) {
                const int sl = PAR + u;              // compile-time
                u64 o, d;
                MUL2(o, C3, W3);
                FMA2(o, C7,  W7,  o);
                FMA2(o, C15, W15, o);
                FMA2(o, C31, W31, o);
                stg_cs64(op + (size_t)sl * 256, o);
                u64 nv = rw[(sl + 17) & 31][lane];          // x[s+17] (LDS.64)
                SUB2(d, Q[(sl + 2)  & 31], Q[(sl + 31) & 31]); ADD2(W3,  W3,  d);
                SUB2(d, Q[(sl + 4)  & 31], Q[(sl + 29) & 31]); ADD2(W7,  W7,  d);
                SUB2(d, Q[(sl + 8)  & 31], Q[(sl + 25) & 31]); ADD2(W15, W15, d);
                SUB2(d, Q[(sl + 16) & 31], Q[(sl + 17) & 31]); ADD2(W31, W31, d);
                Q[(sl + 17) & 31] = nv;
            }

            // stage rows [p+49, p+64] (while any row <= SEG+16 is needed)
            const bool iA = (p_rel + 49 <= SEG + 16);
            const bool iB = (p_rel + 57 <= SEG + 16);
            if (iA) { if (CLAMP) P.issue_clamped(s0 + p_rel + 49);
                      else       P.issue_fast   (s0 + p_rel + 49); }
            if (iB) { if (CLAMP) P.issue_clamped(s0 + p_rel + 57);
                      else       P.issue_fast   (s0 + p_rel + 57); }
            if (iA) {
                cp_wait<2>();                 // rows <= p+48 complete for next
            } else if (p_rel == SEG - 32) {
                cp_wait<0>();                 // drain final groups (<= SEG+16)
            }
            __syncwarp();
        }
        op += (size_t)32 * 256;
    }
}

__global__ void __launch_bounds__(TPB, 8)
msma_kernel(const float* __restrict__ x,
            const float* __restrict__ kw,
            float* __restrict__ out) {
    // per-warp ring: 32 rows x 64 channels (256B/row) as 32 u64 lane-pairs
    __shared__ u64 ring[2][RING][32];   // 16 KB

    const int lane = threadIdx.x & 31;
    const int warp = threadIdx.x >> 5;
    const int f0   = blockIdx.x * 128 + warp * 64;  // 64 channels per warp
    const int s0   = blockIdx.y * SEG;              // multiple of 512
    const int b    = blockIdx.z;

    // softmax over the 4 kernel weights, folded with 1/k; packed duplicates
    const float k0 = kw[0], k1 = kw[1], k2 = kw[2], k3 = kw[3];
    const float mx = fmaxf(fmaxf(k0, k1), fmaxf(k2, k3));
    const float e0 = __expf(k0 - mx), e1 = __expf(k1 - mx);
    const float e2 = __expf(k2 - mx), e3 = __expf(k3 - mx);
    const float inv = 1.0f / (e0 + e1 + e2 + e3);
    const u64 C3  = pack2(e0 * inv * (1.0f / 3.0f));
    const u64 C7  = pack2(e1 * inv * (1.0f / 7.0f));
    const u64 C15 = pack2(e2 * inv * (1.0f / 15.0f));
    const u64 C31 = pack2(e3 * inv * (1.0f / 31.0f));

    u64 (* __restrict__ rw)[32] = ring[warp];

    Prod P;
    P.xb    = x + (size_t)b * S_DIM * F_DIM;
    P.pol   = mk_evict_first_policy();
    P.prow  = lane >> 4;            // 0..1 (row within round)
    P.pcolf = (lane & 15) << 2;     // float offset 0,4,..,60 within row
    P.f0    = f0;
    P.rbase = (unsigned)__cvta_generic_to_shared(&ring[warp][0][0]);
    P.pbyte = (unsigned)(P.pcolf << 2);

    // ---- Prologue phase 1: rows [s0-15, s0+16] fill the whole ring ----
    P.issue_clamped(s0 - 15); P.issue_clamped(s0 - 7);
    P.issue_clamped(s0 + 1);  P.issue_clamped(s0 + 9);
    cp_wait<0>();
    __syncwarp();

    // Q[row & 31] = packed x[row] for rows s0-15 .. s0+16  (s0 % 32 == 0)
    u64 Q[32];
    #pragma unroll
    for (int i = 0; i < 32; ++i) Q[i] = rw[i][lane];

    // initial packed window sums at s = s0 (slot of s0+t is t & 31)
    u64 W3, W7, W15, W31, tmp;
    ADD2(tmp, Q[31], Q[0]);  ADD2(W3, tmp, Q[1]);
    W7 = W3;
    #pragma unroll
    for (int t = 2; t <= 3; ++t)  { ADD2(tmp, Q[t], Q[32 - t]); ADD2(W7,  W7,  tmp); }
    W15 = W7;
    #pragma unroll
    for (int t = 4; t <= 7; ++t)  { ADD2(tmp, Q[t], Q[32 - t]); ADD2(W15, W15, tmp); }
    W31 = W15;
    #pragma unroll
    for (int t = 8; t <= 15; ++t) { ADD2(tmp, Q[t], Q[32 - t]); ADD2(W31, W31, tmp); }

    __syncwarp();   // whole ring consumed into Q; all slots reusable

    // ---- Prologue phase 2: issue rows [s0+17, s0+48] (4 groups) ----
    // rows 17..48 never OOB (max s0 = 3584 -> s0+48 = 3632 < 4096)
    P.issue_fast(s0 + 17); P.issue_fast(s0 + 25);
    P.issue_fast(s0 + 33); P.issue_fast(s0 + 41);
    cp_wait<2>();            // rows <= s0+32 complete; (s0+32, s0+48] pending
    __syncwarp();

    // output pointer, u64 granularity (row = 256 u64)
    u64* __restrict__ op = (u64*)(out + ((size_t)b * S_DIM + s0) * F_DIM + f0)
                           + lane;

    // Main loop: only the last Y-block ever stages rows > S-1.
    if (s0 + SEG + 16 <= S_DIM) {
        main_loop<false>(P, rw, lane, s0, op, Q, C3, C7, C15, C31,
                         W3, W7, W15, W31);
    } else {
        main_loop<true >(P, rw, lane, s0, op, Q, C3, C7, C15, C31,
                         W3, W7, W15, W31);
    }
}

extern "C" void kernel_launch(void* const* d_in, const int* in_sizes, int n_in,
                              void* d_out, int out_size) {
    const float* x  = (const float*)d_in[0];   // [16, 4096, 512] fp32
    const float* kw = (const float*)d_in[1];   // [4] fp32
    float* out = (float*)d_out;                // [16, 4096, 512] fp32

    dim3 grid(F_DIM / 128, S_DIM / SEG, B_DIM); // (4, 8, 16) = 512 blocks
    msma_kernel<<<grid, TPB>>>(x, kw, out);
}